// round 5
// baseline (speedup 1.0000x reference)
#include <cuda_runtime.h>
#include <cuda_bf16.h>

// The reference network mathematically collapses: the GNN "layernorm" is over
// a feature axis of size 1, so (y - mean)/sqrt(var+eps) == 0 exactly and
// h == ln_bias[l] after each propagation layer, independent of everything
// upstream (hash grids, SIREN trunk, member heads, all 2M edges).
// Output = softplus(ln_bias[1,0]) * sigmoid((1 - psi_n) * 50), elementwise.
//
// R5: kernel-internal time is invariant (~4.1-4.35us, pure launch/latency
// floor; all pipes ~0%), but bench duration tracks warps-per-SM at retire:
// 64x256 (8 w/SM) -> 6.9us, 128x128 (4 w/SM) -> 4.6us. Push the same lever:
// 256 CTAs x 64 thr -> all co-resident in one wave, spread over all 148 SMs,
// <=2 CTAs (4 warps) per SM, 40 SMs at 2 warps. Body stays the measured-best
// __expf/__fdividef form (16 regs).

__global__ __launch_bounds__(64, 32)
void collapsed_forward_kernel(const float* __restrict__ psi_n,
                              const float* __restrict__ ln_bias,
                              float* __restrict__ out) {
    int i = blockIdx.x * 64 + threadIdx.x;   // exactly 16384 threads = n/4

    // Issue both loads immediately so their DRAM latencies overlap.
    float4 p = reinterpret_cast<const float4*>(psi_n)[i];
    float b = __ldg(&ln_bias[1]);

    float refined = __logf(1.0f + __expf(b));   // softplus(ln_bias[1])

    // refined * sigmoid((1-p)*50);  sigmoid arg negated: (p-1)*50 = fma(p,50,-50)
    float4 r;
    r.x = __fdividef(refined, 1.0f + __expf(fmaf(p.x, 50.0f, -50.0f)));
    r.y = __fdividef(refined, 1.0f + __expf(fmaf(p.y, 50.0f, -50.0f)));
    r.z = __fdividef(refined, 1.0f + __expf(fmaf(p.z, 50.0f, -50.0f)));
    r.w = __fdividef(refined, 1.0f + __expf(fmaf(p.w, 50.0f, -50.0f)));
    reinterpret_cast<float4*>(out)[i] = r;
}

extern "C" void kernel_launch(void* const* d_in, const int* in_sizes, int n_in,
                              void* d_out, int out_size) {
    const float* psi_n   = (const float*)d_in[2];
    const float* ln_bias = (const float*)d_in[25];
    float* out = (float*)d_out;

    int n4 = out_size / 4;          // 16384
    int blocks = n4 / 64;           // 256 CTAs x 64 threads, exact cover
    collapsed_forward_kernel<<<blocks, 64>>>(psi_n, ln_bias, out);
}

// round 6
// speedup vs baseline: 1.0142x; 1.0142x over previous
#include <cuda_runtime.h>
#include <cuda_bf16.h>

// FINAL. The reference network mathematically collapses: the GNN "layernorm"
// is over a feature axis of size 1, so (y - mean)/sqrt(var+eps) == 0 exactly
// and h == ln_bias[l] after each propagation layer, independent of everything
// upstream (hash grids, SIREN trunk, member heads, all 2M graph edges).
// Output = softplus(ln_bias[1,0]) * sigmoid((1 - psi_n) * 50), elementwise.
//
// Measured saturation (R1-R5): kernel time invariant at ~4.1us across 3x
// instruction-count changes (all ncu pipes ~0%, DRAM 0.8%) — pure
// launch-latency floor (T_ovh ~5000cyc + 1 DRAM round-trip). Bench time
// responds only to warps/SM at retire, saturating at 4.58us for <=4 warps/SM
// (128x128 and 256x64 identical). This is the best-measured configuration:
// 256 CTAs x 64 thr, one float4 per thread, __expf/__fdividef body, 16 regs.

__global__ __launch_bounds__(64, 32)
void collapsed_forward_kernel(const float* __restrict__ psi_n,
                              const float* __restrict__ ln_bias,
                              float* __restrict__ out) {
    int i = blockIdx.x * 64 + threadIdx.x;   // exactly 16384 threads = n/4

    // Issue both loads immediately so their DRAM latencies overlap.
    float4 p = reinterpret_cast<const float4*>(psi_n)[i];
    float b = __ldg(&ln_bias[1]);

    float refined = __logf(1.0f + __expf(b));   // softplus(ln_bias[1])

    // refined * sigmoid((1-p)*50); sigmoid arg negated: (p-1)*50 = fma(p,50,-50)
    float4 r;
    r.x = __fdividef(refined, 1.0f + __expf(fmaf(p.x, 50.0f, -50.0f)));
    r.y = __fdividef(refined, 1.0f + __expf(fmaf(p.y, 50.0f, -50.0f)));
    r.z = __fdividef(refined, 1.0f + __expf(fmaf(p.z, 50.0f, -50.0f)));
    r.w = __fdividef(refined, 1.0f + __expf(fmaf(p.w, 50.0f, -50.0f)));
    reinterpret_cast<float4*>(out)[i] = r;
}

extern "C" void kernel_launch(void* const* d_in, const int* in_sizes, int n_in,
                              void* d_out, int out_size) {
    const float* psi_n   = (const float*)d_in[2];
    const float* ln_bias = (const float*)d_in[25];
    float* out = (float*)d_out;

    int n4 = out_size / 4;          // 16384
    int blocks = n4 / 64;           // 256 CTAs x 64 threads, exact cover
    collapsed_forward_kernel<<<blocks, 64>>>(psi_n, ln_bias, out);
}